// round 12
// baseline (speedup 1.0000x reference)
#include <cuda_runtime.h>
#include <cuda_bf16.h>
#include <cuda_fp16.h>
#include <math.h>
#include <cstdint>

#define N_NODES 50000
#define F 256
#define H 8
#define T_TYPES 3
#define E_PER 800000

// ---------------- static device scratch ----------------
__device__ __half g_hf[(size_t)T_TYPES * N_NODES * F];   // fp16 projected features
__device__ float g_gat[(size_t)2 * N_NODES * F];   // types 0,1; type 2 fused
__device__ float g_el[T_TYPES * N_NODES * H];
__device__ float g_er[T_TYPES * N_NODES * H];
__device__ int   g_off[T_TYPES * (N_NODES + 1)];
__device__ int   g_cur[T_TYPES * N_NODES];
__device__ int   g_srcidx[T_TYPES * E_PER];
__device__ int   g_bsum[T_TYPES * 64];
__device__ int   g_bpre[T_TYPES * 64];
__device__ int   g_is64;
// split-bf16 operands
__device__ unsigned short g_xh[(size_t)N_NODES * F];
__device__ unsigned short g_xl[(size_t)N_NODES * F];
__device__ unsigned short g_wh[T_TYPES * F * F];
__device__ unsigned short g_wl[T_TYPES * F * F];

// ---------------- helpers ----------------
__device__ __forceinline__ uint32_t smem_u32(const void* p) {
    uint32_t a;
    asm("{ .reg .u64 t; cvta.to.shared.u64 t, %1; cvt.u32.u64 %0, t; }" : "=r"(a) : "l"(p));
    return a;
}
__device__ __forceinline__ void ldsm_x4(uint32_t* r, uint32_t addr) {
    asm volatile("ldmatrix.sync.aligned.m8n8.x4.shared.b16 {%0,%1,%2,%3}, [%4];"
                 : "=r"(r[0]), "=r"(r[1]), "=r"(r[2]), "=r"(r[3]) : "r"(addr));
}
__device__ __forceinline__ void ldsm_x4_t(uint32_t* r, uint32_t addr) {
    asm volatile("ldmatrix.sync.aligned.m8n8.x4.trans.shared.b16 {%0,%1,%2,%3}, [%4];"
                 : "=r"(r[0]), "=r"(r[1]), "=r"(r[2]), "=r"(r[3]) : "r"(addr));
}
__device__ __forceinline__ void mma_bf16(float* d, const uint32_t* a, const uint32_t* b) {
    asm volatile(
        "mma.sync.aligned.m16n8k16.row.col.f32.bf16.bf16.f32 "
        "{%0,%1,%2,%3}, {%4,%5,%6,%7}, {%8,%9}, {%0,%1,%2,%3};"
        : "+f"(d[0]), "+f"(d[1]), "+f"(d[2]), "+f"(d[3])
        : "r"(a[0]), "r"(a[1]), "r"(a[2]), "r"(a[3]), "r"(b[0]), "r"(b[1]));
}
__device__ __forceinline__ void cp_async16(uint32_t dst, const void* src, bool pred) {
    int sz = pred ? 16 : 0;
    asm volatile("cp.async.cg.shared.global [%0], [%1], 16, %2;"
                 :: "r"(dst), "l"(src), "r"(sz) : "memory");
}
__device__ __forceinline__ void cp_commit() {
    asm volatile("cp.async.commit_group;" ::: "memory");
}

// ---------------- adj dtype detection ----------------
__global__ void detect_kernel(const int* __restrict__ a) {
    __shared__ int s;
    if (threadIdx.x == 0) s = 0;
    __syncthreads();
    int v = 0;
    for (int i = threadIdx.x; i < 4096; i += 256) v |= a[2 * i + 1];
    atomicOr(&s, v);
    __syncthreads();
    if (threadIdx.x == 0) g_is64 = (s == 0) ? 1 : 0;
}
__device__ __forceinline__ int edge_val(const void* adj, long long idx) {
    if (g_is64) return (int)((const long long*)adj)[idx];
    return ((const int*)adj)[idx];
}

// ---------------- split-bf16 conversions ----------------
__device__ __forceinline__ void split4(float4 v, unsigned short* h, unsigned short* l) {
    float va[4] = {v.x, v.y, v.z, v.w};
#pragma unroll
    for (int i = 0; i < 4; i++) {
        __nv_bfloat16 hb = __float2bfloat16_rn(va[i]);
        __nv_bfloat16 lb = __float2bfloat16_rn(va[i] - __bfloat162float(hb));
        h[i] = __bfloat16_as_ushort(hb);
        l[i] = __bfloat16_as_ushort(lb);
    }
}

__global__ void convert_x_kernel(const float* __restrict__ X) {
    size_t i = ((size_t)blockIdx.x * 256 + threadIdx.x) * 4;
    if (i >= (size_t)N_NODES * F) return;
    float4 v = *(const float4*)(X + i);
    unsigned short h[4], l[4];
    split4(v, h, l);
    *(uint2*)(g_xh + i) = *(const uint2*)h;
    *(uint2*)(g_xl + i) = *(const uint2*)l;
}

__global__ void convert_w_kernel(const float* __restrict__ Ws) {
    size_t i = ((size_t)blockIdx.x * 256 + threadIdx.x) * 4;
    if (i >= (size_t)T_TYPES * F * F) return;
    float4 v = *(const float4*)(Ws + i);
    unsigned short h[4], l[4];
    split4(v, h, l);
    *(uint2*)(g_wh + i) = *(const uint2*)h;
    *(uint2*)(g_wl + i) = *(const uint2*)l;
}

// ---------------- mma.sync GEMM, cp.async double-buffered, 2 CTAs/SM ----------------
#define KC 32
#define A_STRIDE 40
#define B_STRIDE 136
#define BUF_USH (2 * 128 * A_STRIDE + 2 * KC * B_STRIDE)
#define OFF_AH 0
#define OFF_AL (128 * A_STRIDE)
#define OFF_BH (2 * 128 * A_STRIDE)
#define OFF_BL (2 * 128 * A_STRIDE + KC * B_STRIDE)
#define GEMM_SMEM (2 * BUF_USH * 2)

__global__ void __launch_bounds__(256, 2) gemm_mma(int t) {
    extern __shared__ unsigned short sm[];
    const int tid = threadIdx.x;
    const int lane = tid & 31, wid = tid >> 5;
    const int wm = wid & 3, wn = wid >> 2;
    const int row0 = blockIdx.x * 128;
    const int col0 = blockIdx.y * 128;

    const unsigned short* Wh = g_wh + (size_t)t * F * F;
    const unsigned short* Wl = g_wl + (size_t)t * F * F;
    const uint32_t smb = smem_u32(sm);

    const int ar = tid >> 2, acc_ = (tid & 3) * 8;
    const int bk = tid >> 4, bcc = (tid & 15) * 8;

    float c[2][8][4];
#pragma unroll
    for (int mi = 0; mi < 2; mi++)
#pragma unroll
        for (int ni = 0; ni < 8; ni++)
#pragma unroll
            for (int k = 0; k < 4; k++) c[mi][ni][k] = 0.f;

    auto issue = [&](int buf, int chunk) {
        const int k0 = chunk * KC;
        const uint32_t base = smb + (uint32_t)(buf * BUF_USH) * 2;
#pragma unroll
        for (int j = 0; j < 2; j++) {
            int r = ar + j * 64;
            int gr = row0 + r;
            bool ok = gr < N_NODES;
            size_t gidx = (size_t)gr * F + k0 + acc_;
            uint32_t doff = base + (uint32_t)((r * A_STRIDE + acc_) * 2);
            cp_async16(doff + OFF_AH * 2, g_xh + gidx, ok);
            cp_async16(doff + OFF_AL * 2, g_xl + gidx, ok);
        }
#pragma unroll
        for (int j = 0; j < 2; j++) {
            int k = bk + j * 16;
            size_t gidx = (size_t)(k0 + k) * F + col0 + bcc;
            uint32_t doff = base + (uint32_t)((k * B_STRIDE + bcc) * 2);
            cp_async16(doff + OFF_BH * 2, Wh + gidx, true);
            cp_async16(doff + OFF_BL * 2, Wl + gidx, true);
        }
        cp_commit();
    };

    issue(0, 0);

    const int NCHUNK = F / KC;
    for (int chunk = 0; chunk < NCHUNK; chunk++) {
        const int buf = chunk & 1;
        if (chunk < NCHUNK - 1) {
            issue(buf ^ 1, chunk + 1);
            asm volatile("cp.async.wait_group 1;" ::: "memory");
        } else {
            asm volatile("cp.async.wait_group 0;" ::: "memory");
        }
        __syncthreads();

        const uint32_t AHb = smb + (buf * BUF_USH + OFF_AH) * 2;
        const uint32_t ALb = smb + (buf * BUF_USH + OFF_AL) * 2;
        const uint32_t BHb = smb + (buf * BUF_USH + OFF_BH) * 2;
        const uint32_t BLb = smb + (buf * BUF_USH + OFF_BL) * 2;

#pragma unroll
        for (int ks = 0; ks < KC; ks += 16) {
            uint32_t ah[2][4], al[2][4];
#pragma unroll
            for (int mi = 0; mi < 2; mi++) {
                uint32_t off = (uint32_t)(((wm * 32 + mi * 16 + (lane & 15)) * A_STRIDE +
                                           ks + (lane >> 4) * 8) * 2);
                ldsm_x4(ah[mi], AHb + off);
                ldsm_x4(al[mi], ALb + off);
            }
            uint32_t bh[4][4], bl[4][4];
#pragma unroll
            for (int ng = 0; ng < 4; ng++) {
                uint32_t off = (uint32_t)(((ks + (lane & 15)) * B_STRIDE +
                                           wn * 64 + ng * 16 + (lane >> 4) * 8) * 2);
                ldsm_x4_t(bh[ng], BHb + off);
                ldsm_x4_t(bl[ng], BLb + off);
            }
#pragma unroll
            for (int mi = 0; mi < 2; mi++)
#pragma unroll
                for (int ni = 0; ni < 8; ni++) {
                    const uint32_t* bhp = &bh[ni >> 1][(ni & 1) * 2];
                    const uint32_t* blp = &bl[ni >> 1][(ni & 1) * 2];
                    mma_bf16(c[mi][ni], ah[mi], bhp);
                    mma_bf16(c[mi][ni], ah[mi], blp);
                    mma_bf16(c[mi][ni], al[mi], bhp);
                }
        }
        __syncthreads();
    }

    // ---- epilogue: write h as fp16 ----
    __half* outp = g_hf + (size_t)t * N_NODES * F;
    const int rb = row0 + wm * 32 + (lane >> 2);
    const int cb = col0 + wn * 64 + (lane & 3) * 2;
#pragma unroll
    for (int mi = 0; mi < 2; mi++) {
        int r0 = rb + mi * 16;
#pragma unroll
        for (int ni = 0; ni < 8; ni++) {
            int col = cb + ni * 8;
            if (r0 < N_NODES)
                *(__half2*)(outp + (size_t)r0 * F + col) =
                    __floats2half2_rn(c[mi][ni][0], c[mi][ni][1]);
            if (r0 + 8 < N_NODES)
                *(__half2*)(outp + (size_t)(r0 + 8) * F + col) =
                    __floats2half2_rn(c[mi][ni][2], c[mi][ni][3]);
        }
    }
}

// ---------------- per-node attention scores ----------------
__global__ void scores_kernel(const float* __restrict__ al_all, const float* __restrict__ ar_all,
                              int t) {
    int warp = (blockIdx.x * blockDim.x + threadIdx.x) >> 5;
    int lane = threadIdx.x & 31;
    if (warp >= N_NODES) return;
    const __half* hrow = g_hf + ((size_t)t * N_NODES + warp) * F;
    const float* al = al_all + t * F;
    const float* ar = ar_all + t * F;
#pragma unroll
    for (int h = 0; h < H; h++) {
        float v = __half2float(hrow[h * 32 + lane]);
        float pl = v * al[h * 32 + lane];
        float pr = v * ar[h * 32 + lane];
#pragma unroll
        for (int o = 16; o; o >>= 1) {
            pl += __shfl_xor_sync(0xFFFFFFFFu, pl, o);
            pr += __shfl_xor_sync(0xFFFFFFFFu, pr, o);
        }
        if (lane == 0) {
            g_el[(t * N_NODES + warp) * H + h] = pl;
            g_er[(t * N_NODES + warp) * H + h] = pr;
        }
    }
}

// ---------------- CSR build ----------------
__global__ void zero_kernel() {
    int t = blockIdx.y;
    int i = blockIdx.x * blockDim.x + threadIdx.x;
    if (i < N_NODES) g_cur[t * N_NODES + i] = 0;
}

__global__ void hist_kernel(const void* __restrict__ adj) {
    int t = blockIdx.y;
    int e = blockIdx.x * blockDim.x + threadIdx.x;
    if (e < E_PER) {
        int d = edge_val(adj, (long long)(t * 2 + 1) * E_PER + e);
        atomicAdd(&g_cur[t * N_NODES + d], 1);
    }
}

__global__ void scan1_kernel() {
    __shared__ int s[1024];
    int t = blockIdx.y, b = blockIdx.x, tid = threadIdx.x;
    int i = b * 1024 + tid;
    int v = (i < N_NODES) ? g_cur[t * N_NODES + i] : 0;
    int x = v;
    s[tid] = x;
    __syncthreads();
#pragma unroll
    for (int o = 1; o < 1024; o <<= 1) {
        int tv = (tid >= o) ? s[tid - o] : 0;
        __syncthreads();
        x += tv;
        s[tid] = x;
        __syncthreads();
    }
    if (i < N_NODES) g_off[t * (N_NODES + 1) + i] = x - v;
    if (tid == 1023) g_bsum[t * 64 + b] = x;
}

__global__ void scan2_kernel() {
    __shared__ int s[64];
    int t = blockIdx.y, tid = threadIdx.x;
    int v = (tid < 49) ? g_bsum[t * 64 + tid] : 0;
    int x = v;
    s[tid] = x;
    __syncthreads();
#pragma unroll
    for (int o = 1; o < 64; o <<= 1) {
        int tv = (tid >= o) ? s[tid - o] : 0;
        __syncthreads();
        x += tv;
        s[tid] = x;
        __syncthreads();
    }
    if (tid < 49) g_bpre[t * 64 + tid] = x - v;
}

__global__ void scan3_kernel() {
    int t = blockIdx.y, b = blockIdx.x, tid = threadIdx.x;
    int i = b * 1024 + tid;
    if (i < N_NODES) {
        int v = g_off[t * (N_NODES + 1) + i] + g_bpre[t * 64 + b];
        g_off[t * (N_NODES + 1) + i] = v;
        g_cur[t * N_NODES + i] = v;
    }
    if (b == 0 && tid == 0) g_off[t * (N_NODES + 1) + N_NODES] = E_PER;
}

__global__ void scatter_kernel(const void* __restrict__ adj) {
    int t = blockIdx.y;
    int e = blockIdx.x * blockDim.x + threadIdx.x;
    if (e < E_PER) {
        int d = edge_val(adj, (long long)(t * 2 + 1) * E_PER + e);
        int s = edge_val(adj, (long long)(t * 2) * E_PER + e);
        int pos = atomicAdd(&g_cur[t * N_NODES + d], 1);
        g_srcidx[t * E_PER + pos] = s;
    }
}

// ---------------- gather softmax + aggregation (fp16 h, fp32 accum) ----------------
template <bool FUSE>
__global__ void __launch_bounds__(256) aggregate_kernel(
    const float* __restrict__ bias_all, int t,
    const float* __restrict__ att_w, const float* __restrict__ att_b,
    float* __restrict__ out) {
    __shared__ float s_g2[F];

    const int n = blockIdx.x;
    const int tid = threadIdx.x;
    const int head = tid >> 5;
    const int lane = tid & 31;
    const int eg = lane >> 3;
    const int j = lane & 7;

    const int beg = g_off[t * (N_NODES + 1) + n];
    const int deg = g_off[t * (N_NODES + 1) + n + 1] - beg;
    const float er_h = g_er[(t * N_NODES + n) * H + head];

    const int* srcs = g_srcidx + (size_t)t * E_PER + beg;
    const float* el = g_el + (size_t)t * N_NODES * H;
    const __half* hb = g_hf + (size_t)t * N_NODES * F;
    const float* bias = bias_all + t * F;

    float4 acc = make_float4(0.f, 0.f, 0.f, 0.f);
    float ssum = 0.f;

    for (int c0 = 0; c0 < deg; c0 += 32) {
        const int cn = min(32, deg - c0);
        int sreg = 0;
        float w = 0.f;
        if (lane < cn) {
            sreg = srcs[c0 + lane];
            float e = el[sreg * H + head] + er_h;
            e = (e > 0.f) ? e : 0.2f * e;
            w = __expf(e);
        }
        ssum += w;

#pragma unroll 4
        for (int i = 0; i < cn; i += 4) {
            int s = __shfl_sync(0xFFFFFFFFu, sreg, i + eg);
            float wg = __shfl_sync(0xFFFFFFFFu, w, i + eg);
            uint2 raw = *(const uint2*)(hb + (size_t)s * F + head * 32 + j * 4);
            __half2 p0 = *reinterpret_cast<__half2*>(&raw.x);
            __half2 p1 = *reinterpret_cast<__half2*>(&raw.y);
            float2 f0 = __half22float2(p0);
            float2 f1 = __half22float2(p1);
            acc.x = fmaf(wg, f0.x, acc.x);
            acc.y = fmaf(wg, f0.y, acc.y);
            acc.z = fmaf(wg, f1.x, acc.z);
            acc.w = fmaf(wg, f1.y, acc.w);
        }
    }

#pragma unroll
    for (int o = 16; o; o >>= 1) ssum += __shfl_xor_sync(0xFFFFFFFFu, ssum, o);
#pragma unroll
    for (int o = 8; o <= 16; o <<= 1) {
        acc.x += __shfl_xor_sync(0xFFFFFFFFu, acc.x, o);
        acc.y += __shfl_xor_sync(0xFFFFFFFFu, acc.y, o);
        acc.z += __shfl_xor_sync(0xFFFFFFFFu, acc.z, o);
        acc.w += __shfl_xor_sync(0xFFFFFFFFu, acc.w, o);
    }

    if (lane < 8) {
        const float inv = 1.f / (ssum + 1e-9f);
        float4 bv = *(const float4*)(bias + head * 32 + j * 4);
        float4 o;
        o.x = acc.x * inv + bv.x;
        o.y = acc.y * inv + bv.y;
        o.z = acc.z * inv + bv.z;
        o.w = acc.w * inv + bv.w;
        if (FUSE)
            *(float4*)(&s_g2[head * 32 + j * 4]) = o;
        else
            __stcs((float4*)(g_gat + ((size_t)t * N_NODES + n) * F + head * 32 + j * 4), o);
    }

    if (FUSE) {
        __syncthreads();
        size_t base = (size_t)n * F + tid;
        float v0 = g_gat[base];
        float v1 = g_gat[(size_t)N_NODES * F + base];
        float v2 = s_g2[tid];
        float w = att_w[tid];
        float p0 = v0 * w, p1 = v1 * w, p2 = v2 * w;
#pragma unroll
        for (int o = 16; o; o >>= 1) {
            p0 += __shfl_xor_sync(0xFFFFFFFFu, p0, o);
            p1 += __shfl_xor_sync(0xFFFFFFFFu, p1, o);
            p2 += __shfl_xor_sync(0xFFFFFFFFu, p2, o);
        }
        __shared__ float r0[8], r1[8], r2[8];
        if (lane == 0) { r0[head] = p0; r1[head] = p1; r2[head] = p2; }
        __syncthreads();
        float b = att_b[0];
        float a0 = b, a1 = b, a2 = b;
#pragma unroll
        for (int i = 0; i < 8; i++) { a0 += r0[i]; a1 += r1[i]; a2 += r2[i]; }
        out[base] = a0 * v0 + a1 * v1 + a2 * v2;
    }
}

// ---------------- launch ----------------
extern "C" void kernel_launch(void* const* d_in, const int* in_sizes, int n_in,
                              void* d_out, int out_size) {
    const float* x     = (const float*)d_in[0];
    const void*  adj   = d_in[1];
    const float* Ws    = (const float*)d_in[2];
    const float* al    = (const float*)d_in[3];
    const float* ar    = (const float*)d_in[4];
    const float* bias  = (const float*)d_in[5];
    const float* att_w = (const float*)d_in[6];
    const float* att_b = (const float*)d_in[7];
    float* out = (float*)d_out;

    static bool init_done = false;
    static cudaStream_t s2, sA, sB;
    static cudaEvent_t ev_fork, ev_csr, e0, e1, a0, a1;
    if (!init_done) {
        cudaFuncSetAttribute(gemm_mma, cudaFuncAttributeMaxDynamicSharedMemorySize, GEMM_SMEM);
        cudaStreamCreateWithFlags(&s2, cudaStreamNonBlocking);
        cudaStreamCreateWithFlags(&sA, cudaStreamNonBlocking);
        cudaStreamCreateWithFlags(&sB, cudaStreamNonBlocking);
        cudaEventCreateWithFlags(&ev_fork, cudaEventDisableTiming);
        cudaEventCreateWithFlags(&ev_csr, cudaEventDisableTiming);
        cudaEventCreateWithFlags(&e0, cudaEventDisableTiming);
        cudaEventCreateWithFlags(&e1, cudaEventDisableTiming);
        cudaEventCreateWithFlags(&a0, cudaEventDisableTiming);
        cudaEventCreateWithFlags(&a1, cudaEventDisableTiming);
        init_done = true;
    }

    const dim3 gemm_grid((N_NODES + 127) / 128, 2);
    const int scores_blocks = (N_NODES * 32 + 255) / 256;

    // main: detect (CSR branch needs it too)
    detect_kernel<<<1, 256>>>((const int*)adj);
    cudaEventRecord(ev_fork, 0);
    cudaStreamWaitEvent(s2, ev_fork, 0);

    // s2: CSR build (concurrent with projection path)
    zero_kernel<<<dim3((N_NODES + 255) / 256, T_TYPES), 256, 0, s2>>>();
    hist_kernel<<<dim3((E_PER + 255) / 256, T_TYPES), 256, 0, s2>>>(adj);
    scan1_kernel<<<dim3(49, T_TYPES), 1024, 0, s2>>>();
    scan2_kernel<<<dim3(1, T_TYPES), 64, 0, s2>>>();
    scan3_kernel<<<dim3(49, T_TYPES), 1024, 0, s2>>>();
    scatter_kernel<<<dim3((E_PER + 255) / 256, T_TYPES), 256, 0, s2>>>(adj);
    cudaEventRecord(ev_csr, s2);

    // main: converts + per-type GEMMs
    convert_x_kernel<<<(int)(((size_t)N_NODES * F / 4 + 255) / 256), 256>>>(x);
    convert_w_kernel<<<(int)(((size_t)T_TYPES * F * F / 4 + 255) / 256), 256>>>(Ws);

    gemm_mma<<<gemm_grid, 256, GEMM_SMEM>>>(0);
    cudaEventRecord(e0, 0);
    gemm_mma<<<gemm_grid, 256, GEMM_SMEM>>>(1);
    cudaEventRecord(e1, 0);
    gemm_mma<<<gemm_grid, 256, GEMM_SMEM>>>(2);

    // sA: type-0 pipeline (starts as soon as gemm0 + CSR done)
    cudaStreamWaitEvent(sA, e0, 0);
    cudaStreamWaitEvent(sA, ev_csr, 0);
    scores_kernel<<<scores_blocks, 256, 0, sA>>>(al, ar, 0);
    aggregate_kernel<false><<<N_NODES, 256, 0, sA>>>(bias, 0, att_w, att_b, out);
    cudaEventRecord(a0, sA);

    // sB: type-1 pipeline
    cudaStreamWaitEvent(sB, e1, 0);
    cudaStreamWaitEvent(sB, ev_csr, 0);
    scores_kernel<<<scores_blocks, 256, 0, sB>>>(al, ar, 1);
    aggregate_kernel<false><<<N_NODES, 256, 0, sB>>>(bias, 1, att_w, att_b, out);
    cudaEventRecord(a1, sB);

    // main: type-2 scores after gemm2, then fused aggregate+combine after all deps
    cudaStreamWaitEvent(0, ev_csr, 0);
    scores_kernel<<<scores_blocks, 256>>>(al, ar, 2);
    cudaStreamWaitEvent(0, a0, 0);
    cudaStreamWaitEvent(0, a1, 0);
    aggregate_kernel<true><<<N_NODES, 256>>>(bias, 2, att_w, att_b, out);
}

// round 13
// speedup vs baseline: 1.4240x; 1.4240x over previous
#include <cuda_runtime.h>
#include <cuda_bf16.h>
#include <cuda_fp16.h>
#include <math.h>
#include <cstdint>

#define N_NODES 50000
#define F 256
#define H 8
#define T_TYPES 3
#define E_PER 800000

// ---------------- static device scratch ----------------
__device__ __half g_hf[(size_t)T_TYPES * N_NODES * F];   // fp16 projected features
__device__ float g_gat[(size_t)2 * N_NODES * F];   // types 0,1; type 2 fused
__device__ float g_el[T_TYPES * N_NODES * H];
__device__ float g_er[T_TYPES * N_NODES * H];
__device__ int   g_off[T_TYPES * (N_NODES + 1)];
__device__ int   g_cur[T_TYPES * N_NODES];
__device__ int   g_srcidx[T_TYPES * E_PER];
__device__ int   g_bsum[T_TYPES * 64];
__device__ int   g_bpre[T_TYPES * 64];
__device__ int   g_is64;
// split-bf16 operands
__device__ unsigned short g_xh[(size_t)N_NODES * F];
__device__ unsigned short g_xl[(size_t)N_NODES * F];
__device__ unsigned short g_wh[T_TYPES * F * F];
__device__ unsigned short g_wl[T_TYPES * F * F];

// ---------------- helpers ----------------
__device__ __forceinline__ uint32_t smem_u32(const void* p) {
    uint32_t a;
    asm("{ .reg .u64 t; cvta.to.shared.u64 t, %1; cvt.u32.u64 %0, t; }" : "=r"(a) : "l"(p));
    return a;
}
__device__ __forceinline__ void ldsm_x4(uint32_t* r, uint32_t addr) {
    asm volatile("ldmatrix.sync.aligned.m8n8.x4.shared.b16 {%0,%1,%2,%3}, [%4];"
                 : "=r"(r[0]), "=r"(r[1]), "=r"(r[2]), "=r"(r[3]) : "r"(addr));
}
__device__ __forceinline__ void ldsm_x4_t(uint32_t* r, uint32_t addr) {
    asm volatile("ldmatrix.sync.aligned.m8n8.x4.trans.shared.b16 {%0,%1,%2,%3}, [%4];"
                 : "=r"(r[0]), "=r"(r[1]), "=r"(r[2]), "=r"(r[3]) : "r"(addr));
}
__device__ __forceinline__ void mma_bf16(float* d, const uint32_t* a, const uint32_t* b) {
    asm volatile(
        "mma.sync.aligned.m16n8k16.row.col.f32.bf16.bf16.f32 "
        "{%0,%1,%2,%3}, {%4,%5,%6,%7}, {%8,%9}, {%0,%1,%2,%3};"
        : "+f"(d[0]), "+f"(d[1]), "+f"(d[2]), "+f"(d[3])
        : "r"(a[0]), "r"(a[1]), "r"(a[2]), "r"(a[3]), "r"(b[0]), "r"(b[1]));
}
__device__ __forceinline__ void cp_async16(uint32_t dst, const void* src, bool pred) {
    int sz = pred ? 16 : 0;
    asm volatile("cp.async.cg.shared.global [%0], [%1], 16, %2;"
                 :: "r"(dst), "l"(src), "r"(sz) : "memory");
}
__device__ __forceinline__ void cp_commit() {
    asm volatile("cp.async.commit_group;" ::: "memory");
}

// ---------------- adj dtype detection ----------------
__global__ void detect_kernel(const int* __restrict__ a) {
    __shared__ int s;
    if (threadIdx.x == 0) s = 0;
    __syncthreads();
    int v = 0;
    for (int i = threadIdx.x; i < 4096; i += 256) v |= a[2 * i + 1];
    atomicOr(&s, v);
    __syncthreads();
    if (threadIdx.x == 0) g_is64 = (s == 0) ? 1 : 0;
}
__device__ __forceinline__ int edge_val(const void* adj, long long idx) {
    if (g_is64) return (int)((const long long*)adj)[idx];
    return ((const int*)adj)[idx];
}

// ---------------- split-bf16 conversions ----------------
__device__ __forceinline__ void split4(float4 v, unsigned short* h, unsigned short* l) {
    float va[4] = {v.x, v.y, v.z, v.w};
#pragma unroll
    for (int i = 0; i < 4; i++) {
        __nv_bfloat16 hb = __float2bfloat16_rn(va[i]);
        __nv_bfloat16 lb = __float2bfloat16_rn(va[i] - __bfloat162float(hb));
        h[i] = __bfloat16_as_ushort(hb);
        l[i] = __bfloat16_as_ushort(lb);
    }
}

__global__ void convert_x_kernel(const float* __restrict__ X) {
    size_t i = ((size_t)blockIdx.x * 256 + threadIdx.x) * 4;
    if (i >= (size_t)N_NODES * F) return;
    float4 v = *(const float4*)(X + i);
    unsigned short h[4], l[4];
    split4(v, h, l);
    *(uint2*)(g_xh + i) = *(const uint2*)h;
    *(uint2*)(g_xl + i) = *(const uint2*)l;
}

__global__ void convert_w_kernel(const float* __restrict__ Ws) {
    size_t i = ((size_t)blockIdx.x * 256 + threadIdx.x) * 4;
    if (i >= (size_t)T_TYPES * F * F) return;
    float4 v = *(const float4*)(Ws + i);
    unsigned short h[4], l[4];
    split4(v, h, l);
    *(uint2*)(g_wh + i) = *(const uint2*)h;
    *(uint2*)(g_wl + i) = *(const uint2*)l;
}

// ---------------- mma.sync GEMM, cp.async double-buffered, 2 CTAs/SM ----------------
#define KC 32
#define A_STRIDE 40
#define B_STRIDE 136
#define BUF_USH (2 * 128 * A_STRIDE + 2 * KC * B_STRIDE)
#define OFF_AH 0
#define OFF_AL (128 * A_STRIDE)
#define OFF_BH (2 * 128 * A_STRIDE)
#define OFF_BL (2 * 128 * A_STRIDE + KC * B_STRIDE)
#define GEMM_SMEM (2 * BUF_USH * 2)

__global__ void __launch_bounds__(256, 2) gemm_mma() {
    extern __shared__ unsigned short sm[];
    const int tid = threadIdx.x;
    const int lane = tid & 31, wid = tid >> 5;
    const int wm = wid & 3, wn = wid >> 2;
    const int row0 = blockIdx.x * 128;
    const int col0 = blockIdx.y * 128;
    const int t = blockIdx.z;

    const unsigned short* Wh = g_wh + (size_t)t * F * F;
    const unsigned short* Wl = g_wl + (size_t)t * F * F;
    const uint32_t smb = smem_u32(sm);

    const int ar = tid >> 2, acc_ = (tid & 3) * 8;
    const int bk = tid >> 4, bcc = (tid & 15) * 8;

    float c[2][8][4];
#pragma unroll
    for (int mi = 0; mi < 2; mi++)
#pragma unroll
        for (int ni = 0; ni < 8; ni++)
#pragma unroll
            for (int k = 0; k < 4; k++) c[mi][ni][k] = 0.f;

    auto issue = [&](int buf, int chunk) {
        const int k0 = chunk * KC;
        const uint32_t base = smb + (uint32_t)(buf * BUF_USH) * 2;
#pragma unroll
        for (int j = 0; j < 2; j++) {
            int r = ar + j * 64;
            int gr = row0 + r;
            bool ok = gr < N_NODES;
            size_t gidx = (size_t)gr * F + k0 + acc_;
            uint32_t doff = base + (uint32_t)((r * A_STRIDE + acc_) * 2);
            cp_async16(doff + OFF_AH * 2, g_xh + gidx, ok);
            cp_async16(doff + OFF_AL * 2, g_xl + gidx, ok);
        }
#pragma unroll
        for (int j = 0; j < 2; j++) {
            int k = bk + j * 16;
            size_t gidx = (size_t)(k0 + k) * F + col0 + bcc;
            uint32_t doff = base + (uint32_t)((k * B_STRIDE + bcc) * 2);
            cp_async16(doff + OFF_BH * 2, Wh + gidx, true);
            cp_async16(doff + OFF_BL * 2, Wl + gidx, true);
        }
        cp_commit();
    };

    issue(0, 0);

    const int NCHUNK = F / KC;
    for (int chunk = 0; chunk < NCHUNK; chunk++) {
        const int buf = chunk & 1;
        if (chunk < NCHUNK - 1) {
            issue(buf ^ 1, chunk + 1);
            asm volatile("cp.async.wait_group 1;" ::: "memory");
        } else {
            asm volatile("cp.async.wait_group 0;" ::: "memory");
        }
        __syncthreads();

        const uint32_t AHb = smb + (buf * BUF_USH + OFF_AH) * 2;
        const uint32_t ALb = smb + (buf * BUF_USH + OFF_AL) * 2;
        const uint32_t BHb = smb + (buf * BUF_USH + OFF_BH) * 2;
        const uint32_t BLb = smb + (buf * BUF_USH + OFF_BL) * 2;

#pragma unroll
        for (int ks = 0; ks < KC; ks += 16) {
            uint32_t ah[2][4], al[2][4];
#pragma unroll
            for (int mi = 0; mi < 2; mi++) {
                uint32_t off = (uint32_t)(((wm * 32 + mi * 16 + (lane & 15)) * A_STRIDE +
                                           ks + (lane >> 4) * 8) * 2);
                ldsm_x4(ah[mi], AHb + off);
                ldsm_x4(al[mi], ALb + off);
            }
            uint32_t bh[4][4], bl[4][4];
#pragma unroll
            for (int ng = 0; ng < 4; ng++) {
                uint32_t off = (uint32_t)(((ks + (lane & 15)) * B_STRIDE +
                                           wn * 64 + ng * 16 + (lane >> 4) * 8) * 2);
                ldsm_x4_t(bh[ng], BHb + off);
                ldsm_x4_t(bl[ng], BLb + off);
            }
#pragma unroll
            for (int mi = 0; mi < 2; mi++)
#pragma unroll
                for (int ni = 0; ni < 8; ni++) {
                    const uint32_t* bhp = &bh[ni >> 1][(ni & 1) * 2];
                    const uint32_t* blp = &bl[ni >> 1][(ni & 1) * 2];
                    mma_bf16(c[mi][ni], ah[mi], bhp);
                    mma_bf16(c[mi][ni], ah[mi], blp);
                    mma_bf16(c[mi][ni], al[mi], bhp);
                }
        }
        __syncthreads();
    }

    // ---- epilogue: write h as fp16 ----
    __half* outp = g_hf + (size_t)t * N_NODES * F;
    const int rb = row0 + wm * 32 + (lane >> 2);
    const int cb = col0 + wn * 64 + (lane & 3) * 2;
#pragma unroll
    for (int mi = 0; mi < 2; mi++) {
        int r0 = rb + mi * 16;
#pragma unroll
        for (int ni = 0; ni < 8; ni++) {
            int col = cb + ni * 8;
            if (r0 < N_NODES)
                *(__half2*)(outp + (size_t)r0 * F + col) =
                    __floats2half2_rn(c[mi][ni][0], c[mi][ni][1]);
            if (r0 + 8 < N_NODES)
                *(__half2*)(outp + (size_t)(r0 + 8) * F + col) =
                    __floats2half2_rn(c[mi][ni][2], c[mi][ni][3]);
        }
    }
}

// ---------------- per-node attention scores ----------------
__global__ void scores_kernel(const float* __restrict__ al_all, const float* __restrict__ ar_all) {
    int t = blockIdx.y;
    int warp = (blockIdx.x * blockDim.x + threadIdx.x) >> 5;
    int lane = threadIdx.x & 31;
    if (warp >= N_NODES) return;
    const __half* hrow = g_hf + ((size_t)t * N_NODES + warp) * F;
    const float* al = al_all + t * F;
    const float* ar = ar_all + t * F;
#pragma unroll
    for (int h = 0; h < H; h++) {
        float v = __half2float(hrow[h * 32 + lane]);
        float pl = v * al[h * 32 + lane];
        float pr = v * ar[h * 32 + lane];
#pragma unroll
        for (int o = 16; o; o >>= 1) {
            pl += __shfl_xor_sync(0xFFFFFFFFu, pl, o);
            pr += __shfl_xor_sync(0xFFFFFFFFu, pr, o);
        }
        if (lane == 0) {
            g_el[(t * N_NODES + warp) * H + h] = pl;
            g_er[(t * N_NODES + warp) * H + h] = pr;
        }
    }
}

// ---------------- CSR build ----------------
__global__ void zero_kernel() {
    int t = blockIdx.y;
    int i = blockIdx.x * blockDim.x + threadIdx.x;
    if (i < N_NODES) g_cur[t * N_NODES + i] = 0;
}

__global__ void hist_kernel(const void* __restrict__ adj) {
    int t = blockIdx.y;
    int e = blockIdx.x * blockDim.x + threadIdx.x;
    if (e < E_PER) {
        int d = edge_val(adj, (long long)(t * 2 + 1) * E_PER + e);
        atomicAdd(&g_cur[t * N_NODES + d], 1);
    }
}

__global__ void scan1_kernel() {
    __shared__ int s[1024];
    int t = blockIdx.y, b = blockIdx.x, tid = threadIdx.x;
    int i = b * 1024 + tid;
    int v = (i < N_NODES) ? g_cur[t * N_NODES + i] : 0;
    int x = v;
    s[tid] = x;
    __syncthreads();
#pragma unroll
    for (int o = 1; o < 1024; o <<= 1) {
        int tv = (tid >= o) ? s[tid - o] : 0;
        __syncthreads();
        x += tv;
        s[tid] = x;
        __syncthreads();
    }
    if (i < N_NODES) g_off[t * (N_NODES + 1) + i] = x - v;
    if (tid == 1023) g_bsum[t * 64 + b] = x;
}

__global__ void scan2_kernel() {
    __shared__ int s[64];
    int t = blockIdx.y, tid = threadIdx.x;
    int v = (tid < 49) ? g_bsum[t * 64 + tid] : 0;
    int x = v;
    s[tid] = x;
    __syncthreads();
#pragma unroll
    for (int o = 1; o < 64; o <<= 1) {
        int tv = (tid >= o) ? s[tid - o] : 0;
        __syncthreads();
        x += tv;
        s[tid] = x;
        __syncthreads();
    }
    if (tid < 49) g_bpre[t * 64 + tid] = x - v;
}

__global__ void scan3_kernel() {
    int t = blockIdx.y, b = blockIdx.x, tid = threadIdx.x;
    int i = b * 1024 + tid;
    if (i < N_NODES) {
        int v = g_off[t * (N_NODES + 1) + i] + g_bpre[t * 64 + b];
        g_off[t * (N_NODES + 1) + i] = v;
        g_cur[t * N_NODES + i] = v;
    }
    if (b == 0 && tid == 0) g_off[t * (N_NODES + 1) + N_NODES] = E_PER;
}

__global__ void scatter_kernel(const void* __restrict__ adj) {
    int t = blockIdx.y;
    int e = blockIdx.x * blockDim.x + threadIdx.x;
    if (e < E_PER) {
        int d = edge_val(adj, (long long)(t * 2 + 1) * E_PER + e);
        int s = edge_val(adj, (long long)(t * 2) * E_PER + e);
        int pos = atomicAdd(&g_cur[t * N_NODES + d], 1);
        g_srcidx[t * E_PER + pos] = s;
    }
}

// ---------------- warp-per-node aggregation (fp16 h, fp32 accum) ----------------
// One warp owns one dst node. Lane L owns fp16 cols [8L, 8L+8) (uint4), head = L>>2.
// Per edge: 1 shfl + 1 scalar el load (sector-broadcast) + exp + 1 LDG.128 wave
// (full 512B row) + 8 FMAs. el/h loads both depend only on s -> parallel issue.
// ssum per lane = its head's sum (replicated x4 in the quad, no reduction needed).
// No max-shift (scores O(1); result identical after normalization).
// FUSE (t==2): v2 stays in registers; semantic combine is warp-local; writes out.
template <bool FUSE>
__global__ void __launch_bounds__(256) aggregate_kernel(
    const float* __restrict__ bias_all, int tfix,
    const float* __restrict__ att_w, const float* __restrict__ att_b,
    float* __restrict__ out) {
    const int wid = threadIdx.x >> 5;
    const int lane = threadIdx.x & 31;
    const int n = blockIdx.x * 8 + wid;          // 50000 = 6250*8, exact
    const int t = FUSE ? tfix : blockIdx.y;
    const int head = lane >> 2;

    const int beg = g_off[t * (N_NODES + 1) + n];
    const int deg = g_off[t * (N_NODES + 1) + n + 1] - beg;
    const float er_h = g_er[(t * N_NODES + n) * H + head];

    const int* srcs = g_srcidx + (size_t)t * E_PER + beg;
    const float* el = g_el + (size_t)t * N_NODES * H;
    const __half* hb = g_hf + (size_t)t * N_NODES * F;

    float acc[8];
#pragma unroll
    for (int k = 0; k < 8; k++) acc[k] = 0.f;
    float ssum = 0.f;

    for (int c0 = 0; c0 < deg; c0 += 32) {
        const int cn = min(32, deg - c0);
        int sreg = (lane < cn) ? srcs[c0 + lane] : 0;

#pragma unroll 4
        for (int i = 0; i < cn; i++) {
            int s = __shfl_sync(0xFFFFFFFFu, sreg, i);
            float e = __ldg(el + s * H + head) + er_h;
            e = (e > 0.f) ? e : 0.2f * e;
            float w = __expf(e);
            ssum += w;
            uint4 raw = *(const uint4*)(hb + (size_t)s * F + lane * 8);
            float2 f0 = __half22float2(*reinterpret_cast<__half2*>(&raw.x));
            float2 f1 = __half22float2(*reinterpret_cast<__half2*>(&raw.y));
            float2 f2 = __half22float2(*reinterpret_cast<__half2*>(&raw.z));
            float2 f3 = __half22float2(*reinterpret_cast<__half2*>(&raw.w));
            acc[0] = fmaf(w, f0.x, acc[0]);
            acc[1] = fmaf(w, f0.y, acc[1]);
            acc[2] = fmaf(w, f1.x, acc[2]);
            acc[3] = fmaf(w, f1.y, acc[3]);
            acc[4] = fmaf(w, f2.x, acc[4]);
            acc[5] = fmaf(w, f2.y, acc[5]);
            acc[6] = fmaf(w, f3.x, acc[6]);
            acc[7] = fmaf(w, f3.y, acc[7]);
        }
    }

    const float inv = 1.f / (ssum + 1e-9f);
    const float* bias = bias_all + t * F + lane * 8;
    float4 b0 = *(const float4*)bias;
    float4 b1 = *(const float4*)(bias + 4);
    float v2[8];
    v2[0] = acc[0] * inv + b0.x; v2[1] = acc[1] * inv + b0.y;
    v2[2] = acc[2] * inv + b0.z; v2[3] = acc[3] * inv + b0.w;
    v2[4] = acc[4] * inv + b1.x; v2[5] = acc[5] * inv + b1.y;
    v2[6] = acc[6] * inv + b1.z; v2[7] = acc[7] * inv + b1.w;

    size_t base = (size_t)n * F + lane * 8;

    if (!FUSE) {
        float4 o0 = make_float4(v2[0], v2[1], v2[2], v2[3]);
        float4 o1 = make_float4(v2[4], v2[5], v2[6], v2[7]);
        __stcs((float4*)(g_gat + (size_t)t * N_NODES * F + base), o0);
        __stcs((float4*)(g_gat + (size_t)t * N_NODES * F + base + 4), o1);
    } else {
        // warp-local semantic combine
        float v0[8], v1[8], aw[8];
        {
            float4 a0 = *(const float4*)(g_gat + base);
            float4 a1 = *(const float4*)(g_gat + base + 4);
            float4 c0 = *(const float4*)(g_gat + (size_t)N_NODES * F + base);
            float4 c1 = *(const float4*)(g_gat + (size_t)N_NODES * F + base + 4);
            float4 w0 = *(const float4*)(att_w + lane * 8);
            float4 w1 = *(const float4*)(att_w + lane * 8 + 4);
            v0[0]=a0.x; v0[1]=a0.y; v0[2]=a0.z; v0[3]=a0.w;
            v0[4]=a1.x; v0[5]=a1.y; v0[6]=a1.z; v0[7]=a1.w;
            v1[0]=c0.x; v1[1]=c0.y; v1[2]=c0.z; v1[3]=c0.w;
            v1[4]=c1.x; v1[5]=c1.y; v1[6]=c1.z; v1[7]=c1.w;
            aw[0]=w0.x; aw[1]=w0.y; aw[2]=w0.z; aw[3]=w0.w;
            aw[4]=w1.x; aw[5]=w1.y; aw[6]=w1.z; aw[7]=w1.w;
        }
        float p0 = 0.f, p1 = 0.f, p2 = 0.f;
#pragma unroll
        for (int k = 0; k < 8; k++) {
            p0 = fmaf(v0[k], aw[k], p0);
            p1 = fmaf(v1[k], aw[k], p1);
            p2 = fmaf(v2[k], aw[k], p2);
        }
#pragma unroll
        for (int o = 16; o; o >>= 1) {
            p0 += __shfl_xor_sync(0xFFFFFFFFu, p0, o);
            p1 += __shfl_xor_sync(0xFFFFFFFFu, p1, o);
            p2 += __shfl_xor_sync(0xFFFFFFFFu, p2, o);
        }
        float b = att_b[0];
        float a0s = p0 + b, a1s = p1 + b, a2s = p2 + b;
        float4 o0, o1;
        o0.x = a0s * v0[0] + a1s * v1[0] + a2s * v2[0];
        o0.y = a0s * v0[1] + a1s * v1[1] + a2s * v2[1];
        o0.z = a0s * v0[2] + a1s * v1[2] + a2s * v2[2];
        o0.w = a0s * v0[3] + a1s * v1[3] + a2s * v2[3];
        o1.x = a0s * v0[4] + a1s * v1[4] + a2s * v2[4];
        o1.y = a0s * v0[5] + a1s * v1[5] + a2s * v2[5];
        o1.z = a0s * v0[6] + a1s * v1[6] + a2s * v2[6];
        o1.w = a0s * v0[7] + a1s * v1[7] + a2s * v2[7];
        *(float4*)(out + base) = o0;
        *(float4*)(out + base + 4) = o1;
    }
}

// ---------------- launch ----------------
extern "C" void kernel_launch(void* const* d_in, const int* in_sizes, int n_in,
                              void* d_out, int out_size) {
    const float* x     = (const float*)d_in[0];
    const void*  adj   = d_in[1];
    const float* Ws    = (const float*)d_in[2];
    const float* al    = (const float*)d_in[3];
    const float* ar    = (const float*)d_in[4];
    const float* bias  = (const float*)d_in[5];
    const float* att_w = (const float*)d_in[6];
    const float* att_b = (const float*)d_in[7];
    float* out = (float*)d_out;

    static bool init_done = false;
    static cudaStream_t s2;
    static cudaEvent_t ev_fork, ev_join;
    if (!init_done) {
        cudaFuncSetAttribute(gemm_mma, cudaFuncAttributeMaxDynamicSharedMemorySize, GEMM_SMEM);
        cudaStreamCreateWithFlags(&s2, cudaStreamNonBlocking);
        cudaEventCreateWithFlags(&ev_fork, cudaEventDisableTiming);
        cudaEventCreateWithFlags(&ev_join, cudaEventDisableTiming);
        init_done = true;
    }

    // main stream: detect (needed by CSR branch too)
    detect_kernel<<<1, 256>>>((const int*)adj);

    // fork: CSR build on s2, concurrent with converts + GEMM + scores on main
    cudaEventRecord(ev_fork, 0);
    cudaStreamWaitEvent(s2, ev_fork, 0);

    zero_kernel<<<dim3((N_NODES + 255) / 256, T_TYPES), 256, 0, s2>>>();
    hist_kernel<<<dim3((E_PER + 255) / 256, T_TYPES), 256, 0, s2>>>(adj);
    scan1_kernel<<<dim3(49, T_TYPES), 1024, 0, s2>>>();
    scan2_kernel<<<dim3(1, T_TYPES), 64, 0, s2>>>();
    scan3_kernel<<<dim3(49, T_TYPES), 1024, 0, s2>>>();
    scatter_kernel<<<dim3((E_PER + 255) / 256, T_TYPES), 256, 0, s2>>>(adj);
    cudaEventRecord(ev_join, s2);

    // main stream: projection path
    convert_x_kernel<<<(int)(((size_t)N_NODES * F / 4 + 255) / 256), 256>>>(x);
    convert_w_kernel<<<(int)(((size_t)T_TYPES * F * F / 4 + 255) / 256), 256>>>(Ws);
    gemm_mma<<<dim3((N_NODES + 127) / 128, 2, T_TYPES), 256, GEMM_SMEM>>>();
    scores_kernel<<<dim3((N_NODES * 32 + 255) / 256, T_TYPES), 256>>>(al, ar);

    // join: aggregates need both branches
    cudaStreamWaitEvent(0, ev_join, 0);

    aggregate_kernel<false><<<dim3(N_NODES / 8, 2), 256>>>(bias, 0, att_w, att_b, out);
    aggregate_kernel<true ><<<N_NODES / 8, 256>>>(bias, 2, att_w, att_b, out);
}

// round 14
// speedup vs baseline: 1.6416x; 1.1528x over previous
#include <cuda_runtime.h>
#include <cuda_bf16.h>
#include <cuda_fp16.h>
#include <math.h>
#include <cstdint>

#define N_NODES 50000
#define F 256
#define H 8
#define T_TYPES 3
#define E_PER 800000

// ---------------- static device scratch ----------------
__device__ __half g_hf[(size_t)T_TYPES * N_NODES * F];   // fp16 projected features
__device__ float g_gat[(size_t)2 * N_NODES * F];   // types 0,1; type 2 fused
__device__ float g_el[T_TYPES * N_NODES * H];
__device__ float g_er[T_TYPES * N_NODES * H];
__device__ int   g_off[T_TYPES * (N_NODES + 1)];
__device__ int   g_cur[T_TYPES * N_NODES];
__device__ int   g_srcidx[T_TYPES * E_PER];
__device__ int   g_bsum[T_TYPES * 64];
__device__ int   g_bpre[T_TYPES * 64];
__device__ int   g_is64;
// split-bf16 operands
__device__ unsigned short g_xh[(size_t)N_NODES * F];
__device__ unsigned short g_xl[(size_t)N_NODES * F];
__device__ unsigned short g_wh[T_TYPES * F * F];
__device__ unsigned short g_wl[T_TYPES * F * F];

// ---------------- helpers ----------------
__device__ __forceinline__ uint32_t smem_u32(const void* p) {
    uint32_t a;
    asm("{ .reg .u64 t; cvta.to.shared.u64 t, %1; cvt.u32.u64 %0, t; }" : "=r"(a) : "l"(p));
    return a;
}
__device__ __forceinline__ void ldsm_x4(uint32_t* r, uint32_t addr) {
    asm volatile("ldmatrix.sync.aligned.m8n8.x4.shared.b16 {%0,%1,%2,%3}, [%4];"
                 : "=r"(r[0]), "=r"(r[1]), "=r"(r[2]), "=r"(r[3]) : "r"(addr));
}
__device__ __forceinline__ void ldsm_x4_t(uint32_t* r, uint32_t addr) {
    asm volatile("ldmatrix.sync.aligned.m8n8.x4.trans.shared.b16 {%0,%1,%2,%3}, [%4];"
                 : "=r"(r[0]), "=r"(r[1]), "=r"(r[2]), "=r"(r[3]) : "r"(addr));
}
__device__ __forceinline__ void mma_bf16(float* d, const uint32_t* a, const uint32_t* b) {
    asm volatile(
        "mma.sync.aligned.m16n8k16.row.col.f32.bf16.bf16.f32 "
        "{%0,%1,%2,%3}, {%4,%5,%6,%7}, {%8,%9}, {%0,%1,%2,%3};"
        : "+f"(d[0]), "+f"(d[1]), "+f"(d[2]), "+f"(d[3])
        : "r"(a[0]), "r"(a[1]), "r"(a[2]), "r"(a[3]), "r"(b[0]), "r"(b[1]));
}
__device__ __forceinline__ void cp_async16(uint32_t dst, const void* src, bool pred) {
    int sz = pred ? 16 : 0;
    asm volatile("cp.async.cg.shared.global [%0], [%1], 16, %2;"
                 :: "r"(dst), "l"(src), "r"(sz) : "memory");
}
__device__ __forceinline__ void cp_commit() {
    asm volatile("cp.async.commit_group;" ::: "memory");
}

// ---------------- adj dtype detection ----------------
__global__ void detect_kernel(const int* __restrict__ a) {
    __shared__ int s;
    if (threadIdx.x == 0) s = 0;
    __syncthreads();
    int v = 0;
    for (int i = threadIdx.x; i < 4096; i += 256) v |= a[2 * i + 1];
    atomicOr(&s, v);
    __syncthreads();
    if (threadIdx.x == 0) g_is64 = (s == 0) ? 1 : 0;
}
__device__ __forceinline__ int edge_val(const void* adj, long long idx) {
    if (g_is64) return (int)((const long long*)adj)[idx];
    return ((const int*)adj)[idx];
}

// ---------------- split-bf16 conversions ----------------
__device__ __forceinline__ void split4(float4 v, unsigned short* h, unsigned short* l) {
    float va[4] = {v.x, v.y, v.z, v.w};
#pragma unroll
    for (int i = 0; i < 4; i++) {
        __nv_bfloat16 hb = __float2bfloat16_rn(va[i]);
        __nv_bfloat16 lb = __float2bfloat16_rn(va[i] - __bfloat162float(hb));
        h[i] = __bfloat16_as_ushort(hb);
        l[i] = __bfloat16_as_ushort(lb);
    }
}

__global__ void convert_x_kernel(const float* __restrict__ X) {
    size_t i = ((size_t)blockIdx.x * 256 + threadIdx.x) * 4;
    if (i >= (size_t)N_NODES * F) return;
    float4 v = *(const float4*)(X + i);
    unsigned short h[4], l[4];
    split4(v, h, l);
    *(uint2*)(g_xh + i) = *(const uint2*)h;
    *(uint2*)(g_xl + i) = *(const uint2*)l;
}

__global__ void convert_w_kernel(const float* __restrict__ Ws) {
    size_t i = ((size_t)blockIdx.x * 256 + threadIdx.x) * 4;
    if (i >= (size_t)T_TYPES * F * F) return;
    float4 v = *(const float4*)(Ws + i);
    unsigned short h[4], l[4];
    split4(v, h, l);
    *(uint2*)(g_wh + i) = *(const uint2*)h;
    *(uint2*)(g_wl + i) = *(const uint2*)l;
}

// ---------------- mma.sync GEMM + fused scores epilogue ----------------
#define KC 32
#define A_STRIDE 40
#define B_STRIDE 136
#define BUF_USH (2 * 128 * A_STRIDE + 2 * KC * B_STRIDE)
#define OFF_AH 0
#define OFF_AL (128 * A_STRIDE)
#define OFF_BH (2 * 128 * A_STRIDE)
#define OFF_BL (2 * 128 * A_STRIDE + KC * B_STRIDE)
#define GEMM_SMEM (2 * BUF_USH * 2)

__global__ void __launch_bounds__(256, 2) gemm_mma(const float* __restrict__ al_all,
                                                   const float* __restrict__ ar_all) {
    extern __shared__ unsigned short sm[];
    const int tid = threadIdx.x;
    const int lane = tid & 31, wid = tid >> 5;
    const int wm = wid & 3, wn = wid >> 2;
    const int row0 = blockIdx.x * 128;
    const int col0 = blockIdx.y * 128;
    const int t = blockIdx.z;

    const unsigned short* Wh = g_wh + (size_t)t * F * F;
    const unsigned short* Wl = g_wl + (size_t)t * F * F;
    const uint32_t smb = smem_u32(sm);

    const int ar_ = tid >> 2, acc_ = (tid & 3) * 8;
    const int bk = tid >> 4, bcc = (tid & 15) * 8;

    float c[2][8][4];
#pragma unroll
    for (int mi = 0; mi < 2; mi++)
#pragma unroll
        for (int ni = 0; ni < 8; ni++)
#pragma unroll
            for (int k = 0; k < 4; k++) c[mi][ni][k] = 0.f;

    auto issue = [&](int buf, int chunk) {
        const int k0 = chunk * KC;
        const uint32_t base = smb + (uint32_t)(buf * BUF_USH) * 2;
#pragma unroll
        for (int j = 0; j < 2; j++) {
            int r = ar_ + j * 64;
            int gr = row0 + r;
            bool ok = gr < N_NODES;
            size_t gidx = (size_t)gr * F + k0 + acc_;
            uint32_t doff = base + (uint32_t)((r * A_STRIDE + acc_) * 2);
            cp_async16(doff + OFF_AH * 2, g_xh + gidx, ok);
            cp_async16(doff + OFF_AL * 2, g_xl + gidx, ok);
        }
#pragma unroll
        for (int j = 0; j < 2; j++) {
            int k = bk + j * 16;
            size_t gidx = (size_t)(k0 + k) * F + col0 + bcc;
            uint32_t doff = base + (uint32_t)((k * B_STRIDE + bcc) * 2);
            cp_async16(doff + OFF_BH * 2, Wh + gidx, true);
            cp_async16(doff + OFF_BL * 2, Wl + gidx, true);
        }
        cp_commit();
    };

    issue(0, 0);

    const int NCHUNK = F / KC;
    for (int chunk = 0; chunk < NCHUNK; chunk++) {
        const int buf = chunk & 1;
        if (chunk < NCHUNK - 1) {
            issue(buf ^ 1, chunk + 1);
            asm volatile("cp.async.wait_group 1;" ::: "memory");
        } else {
            asm volatile("cp.async.wait_group 0;" ::: "memory");
        }
        __syncthreads();

        const uint32_t AHb = smb + (buf * BUF_USH + OFF_AH) * 2;
        const uint32_t ALb = smb + (buf * BUF_USH + OFF_AL) * 2;
        const uint32_t BHb = smb + (buf * BUF_USH + OFF_BH) * 2;
        const uint32_t BLb = smb + (buf * BUF_USH + OFF_BL) * 2;

#pragma unroll
        for (int ks = 0; ks < KC; ks += 16) {
            uint32_t ah[2][4], al[2][4];
#pragma unroll
            for (int mi = 0; mi < 2; mi++) {
                uint32_t off = (uint32_t)(((wm * 32 + mi * 16 + (lane & 15)) * A_STRIDE +
                                           ks + (lane >> 4) * 8) * 2);
                ldsm_x4(ah[mi], AHb + off);
                ldsm_x4(al[mi], ALb + off);
            }
            uint32_t bh[4][4], bl[4][4];
#pragma unroll
            for (int ng = 0; ng < 4; ng++) {
                uint32_t off = (uint32_t)(((ks + (lane & 15)) * B_STRIDE +
                                           wn * 64 + ng * 16 + (lane >> 4) * 8) * 2);
                ldsm_x4_t(bh[ng], BHb + off);
                ldsm_x4_t(bl[ng], BLb + off);
            }
#pragma unroll
            for (int mi = 0; mi < 2; mi++)
#pragma unroll
                for (int ni = 0; ni < 8; ni++) {
                    const uint32_t* bhp = &bh[ni >> 1][(ni & 1) * 2];
                    const uint32_t* blp = &bl[ni >> 1][(ni & 1) * 2];
                    mma_bf16(c[mi][ni], ah[mi], bhp);
                    mma_bf16(c[mi][ni], ah[mi], blp);
                    mma_bf16(c[mi][ni], al[mi], bhp);
                }
        }
        __syncthreads();
    }

    // ---- epilogue A: write h as fp16 ----
    __half* outp = g_hf + (size_t)t * N_NODES * F;
    const int rb = row0 + wm * 32 + (lane >> 2);
    const int cb = col0 + wn * 64 + (lane & 3) * 2;
#pragma unroll
    for (int mi = 0; mi < 2; mi++) {
        int r0 = rb + mi * 16;
#pragma unroll
        for (int ni = 0; ni < 8; ni++) {
            int col = cb + ni * 8;
            if (r0 < N_NODES)
                *(__half2*)(outp + (size_t)r0 * F + col) =
                    __floats2half2_rn(c[mi][ni][0], c[mi][ni][1]);
            if (r0 + 8 < N_NODES)
                *(__half2*)(outp + (size_t)(r0 + 8) * F + col) =
                    __floats2half2_rn(c[mi][ni][2], c[mi][ni][3]);
        }
    }

    // ---- epilogue B: fused attention scores ----
    // This block covers heads (by*4 + wn*2 + g), g in {0,1}; head = 32 cols = 4 ni.
    {
        const float* alp = al_all + t * F + col0 + wn * 64;
        const float* arp = ar_all + t * F + col0 + wn * 64;
#pragma unroll
        for (int g = 0; g < 2; g++) {
            float pl[2][2] = {{0.f, 0.f}, {0.f, 0.f}};
            float pr[2][2] = {{0.f, 0.f}, {0.f, 0.f}};
#pragma unroll
            for (int nq = 0; nq < 4; nq++) {
                int ni = g * 4 + nq;
                int cofs = ni * 8 + (lane & 3) * 2;
#pragma unroll
                for (int kk = 0; kk < 2; kk++) {
                    float av = __ldg(alp + cofs + kk);
                    float rv = __ldg(arp + cofs + kk);
#pragma unroll
                    for (int mi = 0; mi < 2; mi++)
#pragma unroll
                        for (int rh = 0; rh < 2; rh++) {
                            pl[mi][rh] = fmaf(c[mi][ni][rh * 2 + kk], av, pl[mi][rh]);
                            pr[mi][rh] = fmaf(c[mi][ni][rh * 2 + kk], rv, pr[mi][rh]);
                        }
                }
            }
            const int head = blockIdx.y * 4 + wn * 2 + g;
#pragma unroll
            for (int mi = 0; mi < 2; mi++)
#pragma unroll
                for (int rh = 0; rh < 2; rh++) {
                    float l = pl[mi][rh], r = pr[mi][rh];
                    l += __shfl_xor_sync(0xFFFFFFFFu, l, 1);
                    l += __shfl_xor_sync(0xFFFFFFFFu, l, 2);
                    r += __shfl_xor_sync(0xFFFFFFFFu, r, 1);
                    r += __shfl_xor_sync(0xFFFFFFFFu, r, 2);
                    int row = rb + mi * 16 + rh * 8;
                    if ((lane & 3) == 0 && row < N_NODES) {
                        g_el[(t * N_NODES + row) * H + head] = l;
                        g_er[(t * N_NODES + row) * H + head] = r;
                    }
                }
        }
    }
}

// ---------------- CSR build ----------------
__global__ void zero_kernel() {
    int t = blockIdx.y;
    int i = blockIdx.x * blockDim.x + threadIdx.x;
    if (i < N_NODES) g_cur[t * N_NODES + i] = 0;
}

__global__ void hist_kernel(const void* __restrict__ adj) {
    int t = blockIdx.y;
    int e = blockIdx.x * blockDim.x + threadIdx.x;
    if (e < E_PER) {
        int d = edge_val(adj, (long long)(t * 2 + 1) * E_PER + e);
        atomicAdd(&g_cur[t * N_NODES + d], 1);
    }
}

__global__ void scan1_kernel() {
    __shared__ int s[1024];
    int t = blockIdx.y, b = blockIdx.x, tid = threadIdx.x;
    int i = b * 1024 + tid;
    int v = (i < N_NODES) ? g_cur[t * N_NODES + i] : 0;
    int x = v;
    s[tid] = x;
    __syncthreads();
#pragma unroll
    for (int o = 1; o < 1024; o <<= 1) {
        int tv = (tid >= o) ? s[tid - o] : 0;
        __syncthreads();
        x += tv;
        s[tid] = x;
        __syncthreads();
    }
    if (i < N_NODES) g_off[t * (N_NODES + 1) + i] = x - v;
    if (tid == 1023) g_bsum[t * 64 + b] = x;
}

__global__ void scan2_kernel() {
    __shared__ int s[64];
    int t = blockIdx.y, tid = threadIdx.x;
    int v = (tid < 49) ? g_bsum[t * 64 + tid] : 0;
    int x = v;
    s[tid] = x;
    __syncthreads();
#pragma unroll
    for (int o = 1; o < 64; o <<= 1) {
        int tv = (tid >= o) ? s[tid - o] : 0;
        __syncthreads();
        x += tv;
        s[tid] = x;
        __syncthreads();
    }
    if (tid < 49) g_bpre[t * 64 + tid] = x - v;
}

__global__ void scan3_kernel() {
    int t = blockIdx.y, b = blockIdx.x, tid = threadIdx.x;
    int i = b * 1024 + tid;
    if (i < N_NODES) {
        int v = g_off[t * (N_NODES + 1) + i] + g_bpre[t * 64 + b];
        g_off[t * (N_NODES + 1) + i] = v;
        g_cur[t * N_NODES + i] = v;
    }
    if (b == 0 && tid == 0) g_off[t * (N_NODES + 1) + N_NODES] = E_PER;
}

__global__ void scatter_kernel(const void* __restrict__ adj) {
    int t = blockIdx.y;
    int e = blockIdx.x * blockDim.x + threadIdx.x;
    if (e < E_PER) {
        int d = edge_val(adj, (long long)(t * 2 + 1) * E_PER + e);
        int s = edge_val(adj, (long long)(t * 2) * E_PER + e);
        int pos = atomicAdd(&g_cur[t * N_NODES + d], 1);
        g_srcidx[t * E_PER + pos] = s;
    }
}

// ---------------- warp-per-node aggregation (fp16 h, fp32 accum) ----------------
// One warp owns one dst node. Lane L owns fp16 cols [8L, 8L+8) (uint4), head = L>>2.
template <bool FUSE>
__global__ void __launch_bounds__(256) aggregate_kernel(
    const float* __restrict__ bias_all, int tfix,
    const float* __restrict__ att_w, const float* __restrict__ att_b,
    float* __restrict__ out) {
    const int wid = threadIdx.x >> 5;
    const int lane = threadIdx.x & 31;
    const int n = blockIdx.x * 8 + wid;          // 50000 = 6250*8, exact
    const int t = FUSE ? tfix : blockIdx.y;
    const int head = lane >> 2;

    const int beg = g_off[t * (N_NODES + 1) + n];
    const int deg = g_off[t * (N_NODES + 1) + n + 1] - beg;
    const float er_h = g_er[(t * N_NODES + n) * H + head];

    const int* srcs = g_srcidx + (size_t)t * E_PER + beg;
    const float* el = g_el + (size_t)t * N_NODES * H;
    const __half* hb = g_hf + (size_t)t * N_NODES * F;

    float acc[8];
#pragma unroll
    for (int k = 0; k < 8; k++) acc[k] = 0.f;
    float ssum = 0.f;

    for (int c0 = 0; c0 < deg; c0 += 32) {
        const int cn = min(32, deg - c0);
        int sreg = (lane < cn) ? srcs[c0 + lane] : 0;

#pragma unroll 4
        for (int i = 0; i < cn; i++) {
            int s = __shfl_sync(0xFFFFFFFFu, sreg, i);
            float e = __ldg(el + s * H + head) + er_h;
            e = (e > 0.f) ? e : 0.2f * e;
            float w = __expf(e);
            ssum += w;
            uint4 raw = *(const uint4*)(hb + (size_t)s * F + lane * 8);
            float2 f0 = __half22float2(*reinterpret_cast<__half2*>(&raw.x));
            float2 f1 = __half22float2(*reinterpret_cast<__half2*>(&raw.y));
            float2 f2 = __half22float2(*reinterpret_cast<__half2*>(&raw.z));
            float2 f3 = __half22float2(*reinterpret_cast<__half2*>(&raw.w));
            acc[0] = fmaf(w, f0.x, acc[0]);
            acc[1] = fmaf(w, f0.y, acc[1]);
            acc[2] = fmaf(w, f1.x, acc[2]);
            acc[3] = fmaf(w, f1.y, acc[3]);
            acc[4] = fmaf(w, f2.x, acc[4]);
            acc[5] = fmaf(w, f2.y, acc[5]);
            acc[6] = fmaf(w, f3.x, acc[6]);
            acc[7] = fmaf(w, f3.y, acc[7]);
        }
    }

    const float inv = 1.f / (ssum + 1e-9f);
    const float* bias = bias_all + t * F + lane * 8;
    float4 b0 = *(const float4*)bias;
    float4 b1 = *(const float4*)(bias + 4);
    float v2[8];
    v2[0] = acc[0] * inv + b0.x; v2[1] = acc[1] * inv + b0.y;
    v2[2] = acc[2] * inv + b0.z; v2[3] = acc[3] * inv + b0.w;
    v2[4] = acc[4] * inv + b1.x; v2[5] = acc[5] * inv + b1.y;
    v2[6] = acc[6] * inv + b1.z; v2[7] = acc[7] * inv + b1.w;

    size_t base = (size_t)n * F + lane * 8;

    if (!FUSE) {
        float4 o0 = make_float4(v2[0], v2[1], v2[2], v2[3]);
        float4 o1 = make_float4(v2[4], v2[5], v2[6], v2[7]);
        __stcs((float4*)(g_gat + (size_t)t * N_NODES * F + base), o0);
        __stcs((float4*)(g_gat + (size_t)t * N_NODES * F + base + 4), o1);
    } else {
        float v0[8], v1[8], aw[8];
        {
            float4 a0 = *(const float4*)(g_gat + base);
            float4 a1 = *(const float4*)(g_gat + base + 4);
            float4 c0 = *(const float4*)(g_gat + (size_t)N_NODES * F + base);
            float4 c1 = *(const float4*)(g_gat + (size_t)N_NODES * F + base + 4);
            float4 w0 = *(const float4*)(att_w + lane * 8);
            float4 w1 = *(const float4*)(att_w + lane * 8 + 4);
            v0[0]=a0.x; v0[1]=a0.y; v0[2]=a0.z; v0[3]=a0.w;
            v0[4]=a1.x; v0[5]=a1.y; v0[6]=a1.z; v0[7]=a1.w;
            v1[0]=c0.x; v1[1]=c0.y; v1[2]=c0.z; v1[3]=c0.w;
            v1[4]=c1.x; v1[5]=c1.y; v1[6]=c1.z; v1[7]=c1.w;
            aw[0]=w0.x; aw[1]=w0.y; aw[2]=w0.z; aw[3]=w0.w;
            aw[4]=w1.x; aw[5]=w1.y; aw[6]=w1.z; aw[7]=w1.w;
        }
        float p0 = 0.f, p1 = 0.f, p2 = 0.f;
#pragma unroll
        for (int k = 0; k < 8; k++) {
            p0 = fmaf(v0[k], aw[k], p0);
            p1 = fmaf(v1[k], aw[k], p1);
            p2 = fmaf(v2[k], aw[k], p2);
        }
#pragma unroll
        for (int o = 16; o; o >>= 1) {
            p0 += __shfl_xor_sync(0xFFFFFFFFu, p0, o);
            p1 += __shfl_xor_sync(0xFFFFFFFFu, p1, o);
            p2 += __shfl_xor_sync(0xFFFFFFFFu, p2, o);
        }
        float b = att_b[0];
        float a0s = p0 + b, a1s = p1 + b, a2s = p2 + b;
        float4 o0, o1;
        o0.x = a0s * v0[0] + a1s * v1[0] + a2s * v2[0];
        o0.y = a0s * v0[1] + a1s * v1[1] + a2s * v2[1];
        o0.z = a0s * v0[2] + a1s * v1[2] + a2s * v2[2];
        o0.w = a0s * v0[3] + a1s * v1[3] + a2s * v2[3];
        o1.x = a0s * v0[4] + a1s * v1[4] + a2s * v2[4];
        o1.y = a0s * v0[5] + a1s * v1[5] + a2s * v2[5];
        o1.z = a0s * v0[6] + a1s * v1[6] + a2s * v2[6];
        o1.w = a0s * v0[7] + a1s * v1[7] + a2s * v2[7];
        *(float4*)(out + base) = o0;
        *(float4*)(out + base + 4) = o1;
    }
}

// ---------------- launch ----------------
extern "C" void kernel_launch(void* const* d_in, const int* in_sizes, int n_in,
                              void* d_out, int out_size) {
    const float* x     = (const float*)d_in[0];
    const void*  adj   = d_in[1];
    const float* Ws    = (const float*)d_in[2];
    const float* al    = (const float*)d_in[3];
    const float* ar    = (const float*)d_in[4];
    const float* bias  = (const float*)d_in[5];
    const float* att_w = (const float*)d_in[6];
    const float* att_b = (const float*)d_in[7];
    float* out = (float*)d_out;

    static bool init_done = false;
    static cudaStream_t s2;
    static cudaEvent_t ev_fork, ev_join;
    if (!init_done) {
        cudaFuncSetAttribute(gemm_mma, cudaFuncAttributeMaxDynamicSharedMemorySize, GEMM_SMEM);
        cudaStreamCreateWithFlags(&s2, cudaStreamNonBlocking);
        cudaEventCreateWithFlags(&ev_fork, cudaEventDisableTiming);
        cudaEventCreateWithFlags(&ev_join, cudaEventDisableTiming);
        init_done = true;
    }

    // fork s2 off the main stream, then run detect + CSR entirely on s2
    cudaEventRecord(ev_fork, 0);
    cudaStreamWaitEvent(s2, ev_fork, 0);

    detect_kernel<<<1, 256, 0, s2>>>((const int*)adj);
    zero_kernel<<<dim3((N_NODES + 255) / 256, T_TYPES), 256, 0, s2>>>();
    hist_kernel<<<dim3((E_PER + 255) / 256, T_TYPES), 256, 0, s2>>>(adj);
    scan1_kernel<<<dim3(49, T_TYPES), 1024, 0, s2>>>();
    scan2_kernel<<<dim3(1, T_TYPES), 64, 0, s2>>>();
    scan3_kernel<<<dim3(49, T_TYPES), 1024, 0, s2>>>();
    scatter_kernel<<<dim3((E_PER + 255) / 256, T_TYPES), 256, 0, s2>>>(adj);
    cudaEventRecord(ev_join, s2);

    // main stream: projection path (GEMM now also produces el/er)
    convert_x_kernel<<<(int)(((size_t)N_NODES * F / 4 + 255) / 256), 256>>>(x);
    convert_w_kernel<<<(int)(((size_t)T_TYPES * F * F / 4 + 255) / 256), 256>>>(Ws);
    gemm_mma<<<dim3((N_NODES + 127) / 128, 2, T_TYPES), 256, GEMM_SMEM>>>(al, ar);

    // join: aggregates need both branches
    cudaStreamWaitEvent(0, ev_join, 0);

    aggregate_kernel<false><<<dim3(N_NODES / 8, 2), 256>>>(bias, 0, att_w, att_b, out);
    aggregate_kernel<true ><<<N_NODES / 8, 256>>>(bias, 2, att_w, att_b, out);
}